// round 14
// baseline (speedup 1.0000x reference)
#include <cuda_runtime.h>
#include <cuda_fp16.h>
#include <math.h>

#define T_STEPS 12
#define N_NODES 50000
#define E_EDGES 800000
#define C_DIM   128
#define H_DIM   128

#define TOTAL_CNT  (T_STEPS * N_NODES)            // 600000
#define TOTAL_ROWS (T_STEPS * N_NODES)            // 600000
#define TOT_EDGES  (T_STEPS * E_EDGES)            // 9.6M
#define NB_SCAN    ((TOTAL_CNT + 1023) / 1024)    // 586
#define N_TILES    ((TOTAL_ROWS + 127) / 128)     // 4688
#define X_ELEMS    (TOTAL_ROWS * 128)             // 76.8M

#define GEMM_VBLKS 1172
#define FILL_BLKS  586

// ---------------- device scratch ----------------
__device__ int    g_counts [TOTAL_CNT];
__device__ int    g_cursor [TOTAL_CNT];
__device__ int    g_offsets[TOTAL_CNT + 1];
__device__ unsigned long long g_scan_state[1024];   // packed flag(<<32)|sum
__device__ int    g_csr    [TOT_EDGES];
__device__ float  g_dinv   [TOTAL_CNT];
__device__ __half g_bufX   [X_ELEMS];
__device__ __half g_bufA   [X_ELEMS];
__device__ __half g_bufB   [X_ELEMS];
__device__ float  g_gseq   [T_STEPS * H_DIM];

// ---------------- helpers ----------------
__device__ __forceinline__ unsigned pack_h2(float a, float b) {
    __half2 h = __floats2half2_rn(a, b);
    return *(unsigned*)&h;
}
__device__ __forceinline__ __half2 u2h(unsigned v) { return *(__half2*)&v; }
__device__ __forceinline__ void u2_to_f4(uint2 u, float* f) {
    float2 a = __half22float2(*(__half2*)&u.x);
    float2 b = __half22float2(*(__half2*)&u.y);
    f[0] = a.x; f[1] = a.y; f[2] = b.x; f[3] = b.y;
}
__device__ __forceinline__ void cp_async16(void* dst, const void* src) {
    unsigned s = (unsigned)__cvta_generic_to_shared(dst);
    asm volatile("cp.async.ca.shared.global [%0], [%1], 16;" :: "r"(s), "l"(src));
}
#define CP_COMMIT() asm volatile("cp.async.commit_group;")
#define CP_WAIT(N)  asm volatile("cp.async.wait_group %0;" :: "n"(N))

// ---------------- FUSED: count degrees (odd blocks) + x fp32->fp16 (even blocks) ----------------
__global__ void count_x2h_kernel(const int* __restrict__ ei_seq,
                                 const float* __restrict__ x)
{
    int bid = blockIdx.x;
    int half_blocks = gridDim.x >> 1;
    int stride = half_blocks * blockDim.x;
    int base = (bid >> 1) * blockDim.x + threadIdx.x;

    if (bid & 1) {
        for (int g = base; g < TOT_EDGES; g += stride) {
            int t = g / E_EDGES;
            int e = g - t * E_EDGES;
            int d = ei_seq[(size_t)t * 2 * E_EDGES + E_EDGES + e];
            atomicAdd(&g_counts[t * N_NODES + d], 1);
        }
    } else {
        for (int i = base; i < X_ELEMS / 4; i += stride) {
            float4 f = ((const float4*)x)[i];
            uint2 o;
            o.x = pack_h2(f.x, f.y);
            o.y = pack_h2(f.z, f.w);
            ((uint2*)g_bufX)[i] = o;
        }
    }
}

// ---------------- single-pass decoupled-lookback scan (+ dinv) ----------------
__global__ void scan_kernel() {
    __shared__ int wt[32];
    __shared__ int s_total;
    __shared__ int s_prefix;
    int lane = threadIdx.x & 31;
    int wid  = threadIdx.x >> 5;
    int bid  = blockIdx.x;
    int gid  = bid * 1024 + threadIdx.x;

    int v = (gid < TOTAL_CNT) ? g_counts[gid] : 0;
    int s = v;
    #pragma unroll
    for (int off = 1; off < 32; off <<= 1) {
        int u = __shfl_up_sync(0xFFFFFFFFu, s, off);
        if (lane >= off) s += u;
    }
    if (lane == 31) wt[wid] = s;
    __syncthreads();
    if (wid == 0) {
        int w = wt[lane];
        int ws = w;
        #pragma unroll
        for (int off = 1; off < 32; off <<= 1) {
            int u = __shfl_up_sync(0xFFFFFFFFu, ws, off);
            if (lane >= off) ws += u;
        }
        wt[lane] = ws - w;
    }
    __syncthreads();
    int excl_local = wt[wid] + (s - v);
    if (threadIdx.x == 1023) s_total = excl_local + v;
    __syncthreads();

    if (threadIdx.x == 0) {
        int total = s_total;
        if (bid == 0) {
            atomicExch(&g_scan_state[0], (2ULL << 32) | (unsigned)total);
            s_prefix = 0;
        } else {
            atomicExch(&g_scan_state[bid], (1ULL << 32) | (unsigned)total);
            int prefix = 0;
            int look = bid - 1;
            while (true) {
                unsigned long long sv;
                do { sv = atomicAdd(&g_scan_state[look], 0ULL); } while ((sv >> 32) == 0ULL);
                prefix += (int)(unsigned)sv;
                if ((sv >> 32) == 2ULL) break;
                look--;
            }
            atomicExch(&g_scan_state[bid], (2ULL << 32) | (unsigned)(total + prefix));
            s_prefix = prefix;
        }
    }
    __syncthreads();

    int excl = s_prefix + excl_local;
    if (gid < TOTAL_CNT) {
        g_offsets[gid] = excl;
        g_dinv[gid]    = rsqrtf((float)(v + 1));
    }
    if (gid == 0) g_offsets[TOTAL_CNT] = TOT_EDGES;
}

// ============ exact R7 GEMM body as a device function ============
__device__ __forceinline__ void gemm_body(const __half* __restrict__ A,
                                          const float* __restrict__ W,
                                          const float* __restrict__ dinv,
                                          __half* __restrict__ Y, int M,
                                          unsigned (*Ws)[8][136],
                                          unsigned (*As)[128][12],
                                          int vbid, int vstride)
{
    const int tid  = threadIdx.x;
    const int lane = tid & 31;
    const int wid  = tid >> 5;
    const int wm   = wid & 3;
    const int wn   = wid >> 2;
    const int g    = lane >> 2;
    const int tig  = lane & 3;

    #pragma unroll
    for (int i = 0; i < 32; i++) {
        int idx = tid + i * 256;
        int pr  = idx >> 7;
        int col = idx & 127;
        float w0 = W[(size_t)(2 * pr)     * 128 + col];
        float w1 = W[(size_t)(2 * pr + 1) * 128 + col];
        Ws[pr >> 3][pr & 7][col] = pack_h2(w0, w1);
    }
    __syncthreads();

    const int am  = tid >> 1;
    const int akw = (tid & 1) * 4;

    for (int tile = vbid; tile < N_TILES; tile += vstride) {
        const int row0 = tile * 128;
        int agr = row0 + am;
        if (agr >= M) agr = 0;
        const __half* Asrc = A + (size_t)agr * 128 + akw * 2;

        cp_async16(&As[0][am][akw], Asrc);
        CP_COMMIT();

        float acc[2][8][4];
        #pragma unroll
        for (int mi = 0; mi < 2; mi++)
            #pragma unroll
            for (int ni = 0; ni < 8; ni++)
                #pragma unroll
                for (int q = 0; q < 4; q++) acc[mi][ni][q] = 0.0f;

        #pragma unroll
        for (int c = 0; c < 8; c++) {
            if (c < 7) {
                cp_async16(&As[(c + 1) & 1][am][akw], Asrc + (c + 1) * 16);
                CP_COMMIT();
                CP_WAIT(1);
            } else {
                CP_WAIT(0);
            }
            __syncthreads();

            const int st = c & 1;
            unsigned afr[2][4];
            #pragma unroll
            for (int mi = 0; mi < 2; mi++) {
                int rm = wm * 32 + mi * 16;
                afr[mi][0] = As[st][rm + g    ][tig    ];
                afr[mi][1] = As[st][rm + g + 8][tig    ];
                afr[mi][2] = As[st][rm + g    ][tig + 4];
                afr[mi][3] = As[st][rm + g + 8][tig + 4];
            }
            unsigned bfr[8][2];
            #pragma unroll
            for (int ni = 0; ni < 8; ni++) {
                int cb = wn * 64 + ni * 8 + g;
                bfr[ni][0] = Ws[c][tig    ][cb];
                bfr[ni][1] = Ws[c][tig + 4][cb];
            }

            #pragma unroll
            for (int mi = 0; mi < 2; mi++)
                #pragma unroll
                for (int ni = 0; ni < 8; ni++) {
                    asm volatile(
                        "mma.sync.aligned.m16n8k16.row.col.f32.f16.f16.f32 "
                        "{%0,%1,%2,%3},{%4,%5,%6,%7},{%8,%9},{%0,%1,%2,%3};"
                        : "+f"(acc[mi][ni][0]), "+f"(acc[mi][ni][1]),
                          "+f"(acc[mi][ni][2]), "+f"(acc[mi][ni][3])
                        : "r"(afr[mi][0]), "r"(afr[mi][1]),
                          "r"(afr[mi][2]), "r"(afr[mi][3]),
                          "r"(bfr[ni][0]), "r"(bfr[ni][1]));
                }
            __syncthreads();
        }

        #pragma unroll
        for (int mi = 0; mi < 2; mi++) {
            #pragma unroll
            for (int hh = 0; hh < 2; hh++) {
                int r = row0 + wm * 32 + mi * 16 + g + hh * 8;
                if (r < M) {
                    float d = dinv[r];
                    #pragma unroll
                    for (int ni = 0; ni < 8; ni++) {
                        int cc = wn * 64 + ni * 8 + 2 * tig;
                        __half2 h = __floats2half2_rn(d * acc[mi][ni][hh * 2 + 0],
                                                      d * acc[mi][ni][hh * 2 + 1]);
                        *(__half2*)(Y + (size_t)r * 128 + cc) = h;
                    }
                }
            }
        }
    }
}

// ---------------- FUSED: fill CSR (every 3rd block) + GEMM1 (R7 body) ----------------
__global__ __launch_bounds__(256, 2)
void fillgemm_kernel(const int* __restrict__ ei_seq,
                     const __half* __restrict__ A,
                     const float* __restrict__ W,
                     const float* __restrict__ dinv,
                     __half* __restrict__ Y, int M)
{
    __shared__ unsigned Ws[8][8][136];
    __shared__ unsigned As[2][128][12];
    int bid = blockIdx.x;
    if (bid % 3 == 2) {
        int fid = bid / 3;
        int stride = FILL_BLKS * 256;
        for (int gi = fid * 256 + (int)threadIdx.x; gi < TOT_EDGES; gi += stride) {
            int t = gi / E_EDGES;
            int e = gi - t * E_EDGES;
            const int* base = ei_seq + (size_t)t * 2 * E_EDGES;
            int sv = base[e];
            int dv = base[E_EDGES + e];
            int f  = t * N_NODES + dv;
            int pos = g_offsets[f] + atomicAdd(&g_cursor[f], 1);
            g_csr[pos] = sv;
        }
    } else {
        int vbid = (bid / 3) * 2 + (bid % 3);
        gemm_body(A, W, dinv, Y, M, Ws, As, vbid, GEMM_VBLKS);
    }
}

// ---------------- standalone GEMM (layer 2, R7 body) ----------------
__global__ __launch_bounds__(256, 2)
void gemm_kernel(const __half* __restrict__ A,
                 const float* __restrict__ W,
                 const float* __restrict__ dinv,
                 __half* __restrict__ Y, int M)
{
    __shared__ unsigned Ws[8][8][136];
    __shared__ unsigned As[2][128][12];
    gemm_body(A, W, dinv, Y, M, Ws, As, blockIdx.x, GEMM_VBLKS);
}

// ---------------- layer-1 aggregation: warp per node, half2 tree accumulation ----------------
__global__ void agg_kernel(const __half* __restrict__ hpAll,
                           const float* __restrict__ bias,
                           const float* __restrict__ dinvAll,
                           const int* __restrict__ offsAll,
                           __half* __restrict__ outAll)
{
    int t    = blockIdx.y;
    int node = (blockIdx.x * blockDim.x + threadIdx.x) >> 5;
    int lane = threadIdx.x & 31;
    if (node >= N_NODES) return;

    const __half* hp   = hpAll   + (size_t)t * N_NODES * 128;
    const float*  dinv = dinvAll + (size_t)t * N_NODES;
    const int*    offs = offsAll + (size_t)t * N_NODES;
    __half*       out  = outAll  + (size_t)t * N_NODES * 128;

    float a[4];
    u2_to_f4(((const uint2*)(hp + (size_t)node * 128))[lane], a);  // self loop (fp32)

    int s = offs[node];
    int e = offs[node + 1];
    int j = s;
    for (; j + 8 <= e; j += 8) {
        int idx[8];
        #pragma unroll
        for (int q = 0; q < 8; q++) idx[q] = __ldg(&g_csr[j + q]);
        uint2 u[8];
        #pragma unroll
        for (int q = 0; q < 8; q++)
            u[q] = __ldg(&((const uint2*)(hp + (size_t)idx[q] * 128))[lane]);
        // fp16 pairwise tree over the 8-edge batch, then one fp32 accumulate
        __half2 sx = __hadd2(__hadd2(u2h(u[0].x), u2h(u[1].x)),
                             __hadd2(u2h(u[2].x), u2h(u[3].x)));
        sx = __hadd2(sx, __hadd2(__hadd2(u2h(u[4].x), u2h(u[5].x)),
                                 __hadd2(u2h(u[6].x), u2h(u[7].x))));
        __half2 sy = __hadd2(__hadd2(u2h(u[0].y), u2h(u[1].y)),
                             __hadd2(u2h(u[2].y), u2h(u[3].y)));
        sy = __hadd2(sy, __hadd2(__hadd2(u2h(u[4].y), u2h(u[5].y)),
                                 __hadd2(u2h(u[6].y), u2h(u[7].y))));
        float2 fx = __half22float2(sx);
        float2 fy = __half22float2(sy);
        a[0] += fx.x; a[1] += fx.y; a[2] += fy.x; a[3] += fy.y;
    }
    if (j + 4 <= e) {
        int idx[4];
        #pragma unroll
        for (int q = 0; q < 4; q++) idx[q] = __ldg(&g_csr[j + q]);
        uint2 u[4];
        #pragma unroll
        for (int q = 0; q < 4; q++)
            u[q] = __ldg(&((const uint2*)(hp + (size_t)idx[q] * 128))[lane]);
        __half2 sx = __hadd2(__hadd2(u2h(u[0].x), u2h(u[1].x)),
                             __hadd2(u2h(u[2].x), u2h(u[3].x)));
        __half2 sy = __hadd2(__hadd2(u2h(u[0].y), u2h(u[1].y)),
                             __hadd2(u2h(u[2].y), u2h(u[3].y)));
        float2 fx = __half22float2(sx);
        float2 fy = __half22float2(sy);
        a[0] += fx.x; a[1] += fx.y; a[2] += fy.x; a[3] += fy.y;
        j += 4;
    }
    for (; j < e; j++) {
        int src = __ldg(&g_csr[j]);
        float v[4];
        u2_to_f4(((const uint2*)(hp + (size_t)src * 128))[lane], v);
        a[0] += v[0]; a[1] += v[1]; a[2] += v[2]; a[3] += v[3];
    }

    float  d = dinv[node];
    float4 b = ((const float4*)bias)[lane];
    uint2 o;
    o.x = pack_h2(fmaxf(fmaf(d, a[0], b.x), 0.0f), fmaxf(fmaf(d, a[1], b.y), 0.0f));
    o.y = pack_h2(fmaxf(fmaf(d, a[2], b.z), 0.0f), fmaxf(fmaf(d, a[3], b.w), 0.0f));
    ((uint2*)(out + (size_t)node * 128))[lane] = o;
}

// ---------------- layer-2 agg + mean pool: warp per node, half2 tree accumulation ----------------
__global__ void agg_pool_kernel(const __half* __restrict__ hpAll,
                                const float* __restrict__ bias,
                                const float* __restrict__ dinvAll,
                                const int* __restrict__ offsAll,
                                float* __restrict__ gseq)
{
    __shared__ float sacc[128];
    int t    = blockIdx.y;
    int lane = threadIdx.x & 31;
    int gw   = blockIdx.x * (blockDim.x >> 5) + (threadIdx.x >> 5);
    int nw   = gridDim.x * (blockDim.x >> 5);

    const __half* hp   = hpAll   + (size_t)t * N_NODES * 128;
    const float*  dinv = dinvAll + (size_t)t * N_NODES;
    const int*    offs = offsAll + (size_t)t * N_NODES;
    float*        gt   = gseq + t * H_DIM;

    if (threadIdx.x < 128) sacc[threadIdx.x] = 0.0f;
    __syncthreads();

    float4 bq = ((const float4*)bias)[lane];
    float pool[4] = {0.f, 0.f, 0.f, 0.f};

    for (int node = gw; node < N_NODES; node += nw) {
        float a[4];
        u2_to_f4(((const uint2*)(hp + (size_t)node * 128))[lane], a);
        int s = offs[node];
        int e = offs[node + 1];
        int j = s;
        for (; j + 8 <= e; j += 8) {
            int idx[8];
            #pragma unroll
            for (int q = 0; q < 8; q++) idx[q] = __ldg(&g_csr[j + q]);
            uint2 u[8];
            #pragma unroll
            for (int q = 0; q < 8; q++)
                u[q] = __ldg(&((const uint2*)(hp + (size_t)idx[q] * 128))[lane]);
            __half2 sx = __hadd2(__hadd2(u2h(u[0].x), u2h(u[1].x)),
                                 __hadd2(u2h(u[2].x), u2h(u[3].x)));
            sx = __hadd2(sx, __hadd2(__hadd2(u2h(u[4].x), u2h(u[5].x)),
                                     __hadd2(u2h(u[6].x), u2h(u[7].x))));
            __half2 sy = __hadd2(__hadd2(u2h(u[0].y), u2h(u[1].y)),
                                 __hadd2(u2h(u[2].y), u2h(u[3].y)));
            sy = __hadd2(sy, __hadd2(__hadd2(u2h(u[4].y), u2h(u[5].y)),
                                     __hadd2(u2h(u[6].y), u2h(u[7].y))));
            float2 fx = __half22float2(sx);
            float2 fy = __half22float2(sy);
            a[0] += fx.x; a[1] += fx.y; a[2] += fy.x; a[3] += fy.y;
        }
        if (j + 4 <= e) {
            int idx[4];
            #pragma unroll
            for (int q = 0; q < 4; q++) idx[q] = __ldg(&g_csr[j + q]);
            uint2 u[4];
            #pragma unroll
            for (int q = 0; q < 4; q++)
                u[q] = __ldg(&((const uint2*)(hp + (size_t)idx[q] * 128))[lane]);
            __half2 sx = __hadd2(__hadd2(u2h(u[0].x), u2h(u[1].x)),
                                 __hadd2(u2h(u[2].x), u2h(u[3].x)));
            __half2 sy = __hadd2(__hadd2(u2h(u[0].y), u2h(u[1].y)),
                                 __hadd2(u2h(u[2].y), u2h(u[3].y)));
            float2 fx = __half22float2(sx);
            float2 fy = __half22float2(sy);
            a[0] += fx.x; a[1] += fx.y; a[2] += fy.x; a[3] += fy.y;
            j += 4;
        }
        for (; j < e; j++) {
            int src = __ldg(&g_csr[j]);
            float v[4];
            u2_to_f4(((const uint2*)(hp + (size_t)src * 128))[lane], v);
            a[0] += v[0]; a[1] += v[1]; a[2] += v[2]; a[3] += v[3];
        }
        float d = dinv[node];
        pool[0] += fmaxf(fmaf(d, a[0], bq.x), 0.0f);
        pool[1] += fmaxf(fmaf(d, a[1], bq.y), 0.0f);
        pool[2] += fmaxf(fmaf(d, a[2], bq.z), 0.0f);
        pool[3] += fmaxf(fmaf(d, a[3], bq.w), 0.0f);
    }

    #pragma unroll
    for (int q = 0; q < 4; q++)
        atomicAdd(&sacc[lane * 4 + q], pool[q]);
    __syncthreads();
    if (threadIdx.x < 128)
        atomicAdd(&gt[threadIdx.x], sacc[threadIdx.x] * (1.0f / (float)N_NODES));
}

// ---------------- GRU over T steps + head ----------------
__global__ void gru_head_kernel(const float* __restrict__ W_ih,
                                const float* __restrict__ W_hh,
                                const float* __restrict__ b_ih,
                                const float* __restrict__ b_hh,
                                const float* __restrict__ W_head,
                                const float* __restrict__ b_head,
                                float* __restrict__ out)
{
    __shared__ float gbuf[128];
    __shared__ float hbuf[128];
    int j = threadIdx.x;
    hbuf[j] = 0.0f;
    __syncthreads();

    for (int t = 0; t < T_STEPS; t++) {
        gbuf[j] = g_gseq[t * H_DIM + j];
        __syncthreads();
        float gir = b_ih[j], giz = b_ih[128 + j], gin = b_ih[256 + j];
        float ghr = b_hh[j], ghz = b_hh[128 + j], ghn = b_hh[256 + j];
        const float* wi0 = W_ih + (size_t)j * 128;
        const float* wi1 = W_ih + (size_t)(128 + j) * 128;
        const float* wi2 = W_ih + (size_t)(256 + j) * 128;
        const float* wh0 = W_hh + (size_t)j * 128;
        const float* wh1 = W_hh + (size_t)(128 + j) * 128;
        const float* wh2 = W_hh + (size_t)(256 + j) * 128;
        #pragma unroll 4
        for (int k = 0; k < 128; k++) {
            float gk = gbuf[k], hk = hbuf[k];
            gir = fmaf(wi0[k], gk, gir);
            giz = fmaf(wi1[k], gk, giz);
            gin = fmaf(wi2[k], gk, gin);
            ghr = fmaf(wh0[k], hk, ghr);
            ghz = fmaf(wh1[k], hk, ghz);
            ghn = fmaf(wh2[k], hk, ghn);
        }
        float r  = 1.0f / (1.0f + expf(-(gir + ghr)));
        float z  = 1.0f / (1.0f + expf(-(giz + ghz)));
        float nn = tanhf(gin + r * ghn);
        float hn = (1.0f - z) * nn + z * hbuf[j];
        __syncthreads();
        hbuf[j] = hn;
        __syncthreads();
    }

    float o = b_head[j];
    const float* wr = W_head + (size_t)j * 128;
    #pragma unroll 4
    for (int k = 0; k < 128; k++) o = fmaf(wr[k], hbuf[k], o);
    out[j] = o;
}

// ---------------- tail cleanup: restore zeroed invariants for next call ----------------
__global__ void cleanup_kernel() {
    int i = blockIdx.x * blockDim.x + threadIdx.x;
    if (i < TOTAL_CNT) { g_counts[i] = 0; g_cursor[i] = 0; }
    if (i < 1024) g_scan_state[i] = 0ULL;
    if (i < T_STEPS * H_DIM) g_gseq[i] = 0.0f;
}

// ---------------- launch ----------------
extern "C" void kernel_launch(void* const* d_in, const int* in_sizes, int n_in,
                              void* d_out, int out_size)
{
    const float* x_seq  = (const float*)d_in[0];
    const int*   ei_seq = (const int*)  d_in[1];
    const float* W1     = (const float*)d_in[2];
    const float* b1     = (const float*)d_in[3];
    const float* W2     = (const float*)d_in[4];
    const float* b2     = (const float*)d_in[5];
    const float* W_ih   = (const float*)d_in[6];
    const float* W_hh   = (const float*)d_in[7];
    const float* b_ih   = (const float*)d_in[8];
    const float* b_hh   = (const float*)d_in[9];
    const float* W_head = (const float*)d_in[10];
    const float* b_head = (const float*)d_in[11];
    float* out = (float*)d_out;

    __half* bufX;  cudaGetSymbolAddress((void**)&bufX, g_bufX);
    __half* bufA;  cudaGetSymbolAddress((void**)&bufA, g_bufA);
    __half* bufB;  cudaGetSymbolAddress((void**)&bufB, g_bufB);
    float*  dinv;  cudaGetSymbolAddress((void**)&dinv, g_dinv);
    int*    offs;  cudaGetSymbolAddress((void**)&offs, g_offsets);
    float*  gseq;  cudaGetSymbolAddress((void**)&gseq, g_gseq);

    const int AGX = (N_NODES * 32 + 255) / 256;        // warp per node
    const int APX = 416;

    count_x2h_kernel<<<4096, 256>>>(ei_seq, x_seq);                              // #0
    scan_kernel<<<NB_SCAN, 1024>>>();                                            // #1
    fillgemm_kernel<<<FILL_BLKS * 3, 256>>>(ei_seq, bufX, W1, dinv, bufA,        // #2
                                            TOTAL_ROWS);
    {
        dim3 g(AGX, T_STEPS);
        agg_kernel<<<g, 256>>>(bufA, b1, dinv, offs, bufB);                      // #3 (profiled)
    }
    gemm_kernel<<<GEMM_VBLKS, 256>>>(bufB, W2, dinv, bufA, TOTAL_ROWS);          // #4
    {
        dim3 g(APX, T_STEPS);
        agg_pool_kernel<<<g, 256>>>(bufA, b2, dinv, offs, gseq);                 // #5
    }
    gru_head_kernel<<<1, 128>>>(W_ih, W_hh, b_ih, b_hh, W_head, b_head, out);    // #6
    cleanup_kernel<<<(TOTAL_CNT + 255) / 256, 256>>>();                          // #7
}

// round 15
// speedup vs baseline: 1.0547x; 1.0547x over previous
#include <cuda_runtime.h>
#include <cuda_fp16.h>
#include <math.h>

#define T_STEPS 12
#define N_NODES 50000
#define E_EDGES 800000
#define C_DIM   128
#define H_DIM   128

#define TOTAL_CNT  (T_STEPS * N_NODES)            // 600000
#define TOTAL_ROWS (T_STEPS * N_NODES)            // 600000
#define TOT_EDGES  (T_STEPS * E_EDGES)            // 9.6M
#define NB_SCAN    ((TOTAL_CNT + 1023) / 1024)    // 586
#define N_TILES    ((TOTAL_ROWS + 127) / 128)     // 4688
#define X_ELEMS    (TOTAL_ROWS * 128)             // 76.8M

// ---------------- device scratch ----------------
__device__ int    g_counts [TOTAL_CNT];
__device__ int    g_cursor [TOTAL_CNT];
__device__ int    g_offsets[TOTAL_CNT + 1];
__device__ int    g_bsums  [1024];
__device__ int    g_bbase  [1024];
__device__ int    g_csr    [TOT_EDGES];
__device__ float  g_dinv   [TOTAL_CNT];
__device__ __half g_bufX   [X_ELEMS];
__device__ __half g_bufA   [X_ELEMS];
__device__ __half g_bufB   [X_ELEMS];
__device__ float  g_gseq   [T_STEPS * H_DIM];

// ---------------- helpers ----------------
__device__ __forceinline__ unsigned pack_h2(float a, float b) {
    __half2 h = __floats2half2_rn(a, b);
    return *(unsigned*)&h;
}
__device__ __forceinline__ __half2 u2h(unsigned v) { return *(__half2*)&v; }
__device__ __forceinline__ void u2_to_f4(uint2 u, float* f) {
    float2 a = __half22float2(*(__half2*)&u.x);
    float2 b = __half22float2(*(__half2*)&u.y);
    f[0] = a.x; f[1] = a.y; f[2] = b.x; f[3] = b.y;
}
__device__ __forceinline__ void cp_async16(void* dst, const void* src) {
    unsigned s = (unsigned)__cvta_generic_to_shared(dst);
    asm volatile("cp.async.ca.shared.global [%0], [%1], 16;" :: "r"(s), "l"(src));
}
#define CP_COMMIT() asm volatile("cp.async.commit_group;")
#define CP_WAIT(N)  asm volatile("cp.async.wait_group %0;" :: "n"(N))

// ---------------- zero counters + gseq ----------------
__global__ void zero_kernel() {
    int i = blockIdx.x * blockDim.x + threadIdx.x;
    if (i < TOTAL_CNT) { g_counts[i] = 0; g_cursor[i] = 0; }
    if (i < T_STEPS * H_DIM) g_gseq[i] = 0.0f;
}

// ---------------- FUSED: count degrees (odd blocks) + x fp32->fp16 (even blocks) ----------------
__global__ void count_x2h_kernel(const int* __restrict__ ei_seq,
                                 const float* __restrict__ x)
{
    int bid = blockIdx.x;
    int half_blocks = gridDim.x >> 1;
    int stride = half_blocks * blockDim.x;
    int base = (bid >> 1) * blockDim.x + threadIdx.x;

    if (bid & 1) {
        for (int g = base; g < TOT_EDGES; g += stride) {
            int t = g / E_EDGES;
            int e = g - t * E_EDGES;
            int d = ei_seq[(size_t)t * 2 * E_EDGES + E_EDGES + e];
            atomicAdd(&g_counts[t * N_NODES + d], 1);
        }
    } else {
        for (int i = base; i < X_ELEMS / 4; i += stride) {
            float4 f = ((const float4*)x)[i];
            uint2 o;
            o.x = pack_h2(f.x, f.y);
            o.y = pack_h2(f.z, f.w);
            ((uint2*)g_bufX)[i] = o;
        }
    }
}

// ---------------- hierarchical scan (scan1 also writes dinv) ----------------
__global__ void scan1_kernel() {
    __shared__ int wt[32];
    int lane = threadIdx.x & 31;
    int wid  = threadIdx.x >> 5;
    int gid  = blockIdx.x * 1024 + threadIdx.x;
    int v = (gid < TOTAL_CNT) ? g_counts[gid] : 0;
    int s = v;
    #pragma unroll
    for (int off = 1; off < 32; off <<= 1) {
        int u = __shfl_up_sync(0xFFFFFFFFu, s, off);
        if (lane >= off) s += u;
    }
    if (lane == 31) wt[wid] = s;
    __syncthreads();
    if (wid == 0) {
        int w = wt[lane];
        int ws = w;
        #pragma unroll
        for (int off = 1; off < 32; off <<= 1) {
            int u = __shfl_up_sync(0xFFFFFFFFu, ws, off);
            if (lane >= off) ws += u;
        }
        wt[lane] = ws - w;
    }
    __syncthreads();
    int excl = wt[wid] + (s - v);
    if (gid < TOTAL_CNT) {
        g_offsets[gid] = excl;
        g_dinv[gid]    = rsqrtf((float)(v + 1));
    }
    if (threadIdx.x == 1023) g_bsums[blockIdx.x] = excl + v;
}

__global__ void scan2_kernel() {
    __shared__ int wt[32];
    int lane = threadIdx.x & 31;
    int wid  = threadIdx.x >> 5;
    int i = threadIdx.x;
    int v = (i < NB_SCAN) ? g_bsums[i] : 0;
    int s = v;
    #pragma unroll
    for (int off = 1; off < 32; off <<= 1) {
        int u = __shfl_up_sync(0xFFFFFFFFu, s, off);
        if (lane >= off) s += u;
    }
    if (lane == 31) wt[wid] = s;
    __syncthreads();
    if (wid == 0) {
        int w = wt[lane];
        int ws = w;
        #pragma unroll
        for (int off = 1; off < 32; off <<= 1) {
            int u = __shfl_up_sync(0xFFFFFFFFu, ws, off);
            if (lane >= off) ws += u;
        }
        wt[lane] = ws - w;
    }
    __syncthreads();
    g_bbase[i] = wt[wid] + (s - v);
}

__global__ void scan3_kernel() {
    int gid = blockIdx.x * 1024 + threadIdx.x;
    if (gid < TOTAL_CNT) g_offsets[gid] += g_bbase[blockIdx.x];
    if (gid == 0) g_offsets[TOTAL_CNT] = TOT_EDGES;
}

// ---------------- fill CSR ----------------
__global__ void fill_all_kernel(const int* __restrict__ ei_seq) {
    int g = blockIdx.x * blockDim.x + threadIdx.x;
    if (g >= TOT_EDGES) return;
    int t = g / E_EDGES;
    int e = g - t * E_EDGES;
    const int* base = ei_seq + (size_t)t * 2 * E_EDGES;
    int sv = base[e];
    int dv = base[E_EDGES + e];
    int f  = t * N_NODES + dv;
    int pos = g_offsets[f] + atomicAdd(&g_cursor[f], 1);
    g_csr[pos] = sv;
}

// ---------------- pipelined fp16 GEMM (exact R7/R12 version) ----------------
__global__ __launch_bounds__(256, 2)
void gemm_f16_kernel(const __half* __restrict__ A,
                     const float* __restrict__ W,
                     const float* __restrict__ dinv,
                     __half* __restrict__ Y, int M)
{
    __shared__ unsigned Ws[8][8][136];
    __shared__ unsigned As[2][128][12];

    const int tid  = threadIdx.x;
    const int lane = tid & 31;
    const int wid  = tid >> 5;
    const int wm   = wid & 3;
    const int wn   = wid >> 2;
    const int g    = lane >> 2;
    const int tig  = lane & 3;

    #pragma unroll
    for (int i = 0; i < 32; i++) {
        int idx = tid + i * 256;
        int pr  = idx >> 7;
        int col = idx & 127;
        float w0 = W[(size_t)(2 * pr)     * 128 + col];
        float w1 = W[(size_t)(2 * pr + 1) * 128 + col];
        Ws[pr >> 3][pr & 7][col] = pack_h2(w0, w1);
    }
    __syncthreads();

    const int am  = tid >> 1;
    const int akw = (tid & 1) * 4;

    for (int tile = blockIdx.x; tile < N_TILES; tile += gridDim.x) {
        const int row0 = tile * 128;
        int agr = row0 + am;
        if (agr >= M) agr = 0;
        const __half* Asrc = A + (size_t)agr * 128 + akw * 2;

        cp_async16(&As[0][am][akw], Asrc);
        CP_COMMIT();

        float acc[2][8][4];
        #pragma unroll
        for (int mi = 0; mi < 2; mi++)
            #pragma unroll
            for (int ni = 0; ni < 8; ni++)
                #pragma unroll
                for (int q = 0; q < 4; q++) acc[mi][ni][q] = 0.0f;

        #pragma unroll
        for (int c = 0; c < 8; c++) {
            if (c < 7) {
                cp_async16(&As[(c + 1) & 1][am][akw], Asrc + (c + 1) * 16);
                CP_COMMIT();
                CP_WAIT(1);
            } else {
                CP_WAIT(0);
            }
            __syncthreads();

            const int st = c & 1;
            unsigned afr[2][4];
            #pragma unroll
            for (int mi = 0; mi < 2; mi++) {
                int rm = wm * 32 + mi * 16;
                afr[mi][0] = As[st][rm + g    ][tig    ];
                afr[mi][1] = As[st][rm + g + 8][tig    ];
                afr[mi][2] = As[st][rm + g    ][tig + 4];
                afr[mi][3] = As[st][rm + g + 8][tig + 4];
            }
            unsigned bfr[8][2];
            #pragma unroll
            for (int ni = 0; ni < 8; ni++) {
                int cb = wn * 64 + ni * 8 + g;
                bfr[ni][0] = Ws[c][tig    ][cb];
                bfr[ni][1] = Ws[c][tig + 4][cb];
            }

            #pragma unroll
            for (int mi = 0; mi < 2; mi++)
                #pragma unroll
                for (int ni = 0; ni < 8; ni++) {
                    asm volatile(
                        "mma.sync.aligned.m16n8k16.row.col.f32.f16.f16.f32 "
                        "{%0,%1,%2,%3},{%4,%5,%6,%7},{%8,%9},{%0,%1,%2,%3};"
                        : "+f"(acc[mi][ni][0]), "+f"(acc[mi][ni][1]),
                          "+f"(acc[mi][ni][2]), "+f"(acc[mi][ni][3])
                        : "r"(afr[mi][0]), "r"(afr[mi][1]),
                          "r"(afr[mi][2]), "r"(afr[mi][3]),
                          "r"(bfr[ni][0]), "r"(bfr[ni][1]));
                }
            __syncthreads();
        }

        #pragma unroll
        for (int mi = 0; mi < 2; mi++) {
            #pragma unroll
            for (int hh = 0; hh < 2; hh++) {
                int r = row0 + wm * 32 + mi * 16 + g + hh * 8;
                if (r < M) {
                    float d = dinv[r];
                    #pragma unroll
                    for (int ni = 0; ni < 8; ni++) {
                        int cc = wn * 64 + ni * 8 + 2 * tig;
                        __half2 h = __floats2half2_rn(d * acc[mi][ni][hh * 2 + 0],
                                                      d * acc[mi][ni][hh * 2 + 1]);
                        *(__half2*)(Y + (size_t)r * 128 + cc) = h;
                    }
                }
            }
        }
    }
}

// ---------------- layer-1 aggregation: warp/node, HADD2 tree, occupancy-capped regs ----------------
__global__ __launch_bounds__(256, 8)
void agg_kernel(const __half* __restrict__ hpAll,
                const float* __restrict__ bias,
                const float* __restrict__ dinvAll,
                const int* __restrict__ offsAll,
                __half* __restrict__ outAll)
{
    int t    = blockIdx.y;
    int node = (blockIdx.x * blockDim.x + threadIdx.x) >> 5;
    int lane = threadIdx.x & 31;
    if (node >= N_NODES) return;

    const __half* hp   = hpAll   + (size_t)t * N_NODES * 128;
    const float*  dinv = dinvAll + (size_t)t * N_NODES;
    const int*    offs = offsAll + (size_t)t * N_NODES;
    __half*       out  = outAll  + (size_t)t * N_NODES * 128;

    float a[4];
    u2_to_f4(((const uint2*)(hp + (size_t)node * 128))[lane], a);  // self loop (fp32)

    int s = offs[node];
    int e = offs[node + 1];
    int j = s;
    for (; j + 8 <= e; j += 8) {
        int idx[8];
        #pragma unroll
        for (int q = 0; q < 8; q++) idx[q] = __ldg(&g_csr[j + q]);
        uint2 u[8];
        #pragma unroll
        for (int q = 0; q < 8; q++)
            u[q] = __ldg(&((const uint2*)(hp + (size_t)idx[q] * 128))[lane]);
        __half2 sx = __hadd2(__hadd2(u2h(u[0].x), u2h(u[1].x)),
                             __hadd2(u2h(u[2].x), u2h(u[3].x)));
        sx = __hadd2(sx, __hadd2(__hadd2(u2h(u[4].x), u2h(u[5].x)),
                                 __hadd2(u2h(u[6].x), u2h(u[7].x))));
        __half2 sy = __hadd2(__hadd2(u2h(u[0].y), u2h(u[1].y)),
                             __hadd2(u2h(u[2].y), u2h(u[3].y)));
        sy = __hadd2(sy, __hadd2(__hadd2(u2h(u[4].y), u2h(u[5].y)),
                                 __hadd2(u2h(u[6].y), u2h(u[7].y))));
        float2 fx = __half22float2(sx);
        float2 fy = __half22float2(sy);
        a[0] += fx.x; a[1] += fx.y; a[2] += fy.x; a[3] += fy.y;
    }
    if (j + 4 <= e) {
        int idx[4];
        #pragma unroll
        for (int q = 0; q < 4; q++) idx[q] = __ldg(&g_csr[j + q]);
        uint2 u[4];
        #pragma unroll
        for (int q = 0; q < 4; q++)
            u[q] = __ldg(&((const uint2*)(hp + (size_t)idx[q] * 128))[lane]);
        __half2 sx = __hadd2(__hadd2(u2h(u[0].x), u2h(u[1].x)),
                             __hadd2(u2h(u[2].x), u2h(u[3].x)));
        __half2 sy = __hadd2(__hadd2(u2h(u[0].y), u2h(u[1].y)),
                             __hadd2(u2h(u[2].y), u2h(u[3].y)));
        float2 fx = __half22float2(sx);
        float2 fy = __half22float2(sy);
        a[0] += fx.x; a[1] += fx.y; a[2] += fy.x; a[3] += fy.y;
        j += 4;
    }
    for (; j < e; j++) {
        int src = __ldg(&g_csr[j]);
        float v[4];
        u2_to_f4(((const uint2*)(hp + (size_t)src * 128))[lane], v);
        a[0] += v[0]; a[1] += v[1]; a[2] += v[2]; a[3] += v[3];
    }

    float  d = dinv[node];
    float4 b = ((const float4*)bias)[lane];
    uint2 o;
    o.x = pack_h2(fmaxf(fmaf(d, a[0], b.x), 0.0f), fmaxf(fmaf(d, a[1], b.y), 0.0f));
    o.y = pack_h2(fmaxf(fmaf(d, a[2], b.z), 0.0f), fmaxf(fmaf(d, a[3], b.w), 0.0f));
    ((uint2*)(out + (size_t)node * 128))[lane] = o;
}

// ---------------- layer-2 agg + mean pool: warp/node, HADD2 tree, capped regs ----------------
__global__ __launch_bounds__(256, 8)
void agg_pool_kernel(const __half* __restrict__ hpAll,
                     const float* __restrict__ bias,
                     const float* __restrict__ dinvAll,
                     const int* __restrict__ offsAll,
                     float* __restrict__ gseq)
{
    __shared__ float sacc[128];
    int t    = blockIdx.y;
    int lane = threadIdx.x & 31;
    int gw   = blockIdx.x * (blockDim.x >> 5) + (threadIdx.x >> 5);
    int nw   = gridDim.x * (blockDim.x >> 5);

    const __half* hp   = hpAll   + (size_t)t * N_NODES * 128;
    const float*  dinv = dinvAll + (size_t)t * N_NODES;
    const int*    offs = offsAll + (size_t)t * N_NODES;
    float*        gt   = gseq + t * H_DIM;

    if (threadIdx.x < 128) sacc[threadIdx.x] = 0.0f;
    __syncthreads();

    float4 bq = ((const float4*)bias)[lane];
    float pool[4] = {0.f, 0.f, 0.f, 0.f};

    for (int node = gw; node < N_NODES; node += nw) {
        float a[4];
        u2_to_f4(((const uint2*)(hp + (size_t)node * 128))[lane], a);
        int s = offs[node];
        int e = offs[node + 1];
        int j = s;
        for (; j + 8 <= e; j += 8) {
            int idx[8];
            #pragma unroll
            for (int q = 0; q < 8; q++) idx[q] = __ldg(&g_csr[j + q]);
            uint2 u[8];
            #pragma unroll
            for (int q = 0; q < 8; q++)
                u[q] = __ldg(&((const uint2*)(hp + (size_t)idx[q] * 128))[lane]);
            __half2 sx = __hadd2(__hadd2(u2h(u[0].x), u2h(u[1].x)),
                                 __hadd2(u2h(u[2].x), u2h(u[3].x)));
            sx = __hadd2(sx, __hadd2(__hadd2(u2h(u[4].x), u2h(u[5].x)),
                                     __hadd2(u2h(u[6].x), u2h(u[7].x))));
            __half2 sy = __hadd2(__hadd2(u2h(u[0].y), u2h(u[1].y)),
                                 __hadd2(u2h(u[2].y), u2h(u[3].y)));
            sy = __hadd2(sy, __hadd2(__hadd2(u2h(u[4].y), u2h(u[5].y)),
                                     __hadd2(u2h(u[6].y), u2h(u[7].y))));
            float2 fx = __half22float2(sx);
            float2 fy = __half22float2(sy);
            a[0] += fx.x; a[1] += fx.y; a[2] += fy.x; a[3] += fy.y;
        }
        if (j + 4 <= e) {
            int idx[4];
            #pragma unroll
            for (int q = 0; q < 4; q++) idx[q] = __ldg(&g_csr[j + q]);
            uint2 u[4];
            #pragma unroll
            for (int q = 0; q < 4; q++)
                u[q] = __ldg(&((const uint2*)(hp + (size_t)idx[q] * 128))[lane]);
            __half2 sx = __hadd2(__hadd2(u2h(u[0].x), u2h(u[1].x)),
                                 __hadd2(u2h(u[2].x), u2h(u[3].x)));
            __half2 sy = __hadd2(__hadd2(u2h(u[0].y), u2h(u[1].y)),
                                 __hadd2(u2h(u[2].y), u2h(u[3].y)));
            float2 fx = __half22float2(sx);
            float2 fy = __half22float2(sy);
            a[0] += fx.x; a[1] += fx.y; a[2] += fy.x; a[3] += fy.y;
            j += 4;
        }
        for (; j < e; j++) {
            int src = __ldg(&g_csr[j]);
            float v[4];
            u2_to_f4(((const uint2*)(hp + (size_t)src * 128))[lane], v);
            a[0] += v[0]; a[1] += v[1]; a[2] += v[2]; a[3] += v[3];
        }
        float d = dinv[node];
        pool[0] += fmaxf(fmaf(d, a[0], bq.x), 0.0f);
        pool[1] += fmaxf(fmaf(d, a[1], bq.y), 0.0f);
        pool[2] += fmaxf(fmaf(d, a[2], bq.z), 0.0f);
        pool[3] += fmaxf(fmaf(d, a[3], bq.w), 0.0f);
    }

    #pragma unroll
    for (int q = 0; q < 4; q++)
        atomicAdd(&sacc[lane * 4 + q], pool[q]);
    __syncthreads();
    if (threadIdx.x < 128)
        atomicAdd(&gt[threadIdx.x], sacc[threadIdx.x] * (1.0f / (float)N_NODES));
}

// ---------------- GRU over T steps + head ----------------
__global__ void gru_head_kernel(const float* __restrict__ W_ih,
                                const float* __restrict__ W_hh,
                                const float* __restrict__ b_ih,
                                const float* __restrict__ b_hh,
                                const float* __restrict__ W_head,
                                const float* __restrict__ b_head,
                                float* __restrict__ out)
{
    __shared__ float gbuf[128];
    __shared__ float hbuf[128];
    int j = threadIdx.x;
    hbuf[j] = 0.0f;
    __syncthreads();

    for (int t = 0; t < T_STEPS; t++) {
        gbuf[j] = g_gseq[t * H_DIM + j];
        __syncthreads();
        float gir = b_ih[j], giz = b_ih[128 + j], gin = b_ih[256 + j];
        float ghr = b_hh[j], ghz = b_hh[128 + j], ghn = b_hh[256 + j];
        const float* wi0 = W_ih + (size_t)j * 128;
        const float* wi1 = W_ih + (size_t)(128 + j) * 128;
        const float* wi2 = W_ih + (size_t)(256 + j) * 128;
        const float* wh0 = W_hh + (size_t)j * 128;
        const float* wh1 = W_hh + (size_t)(128 + j) * 128;
        const float* wh2 = W_hh + (size_t)(256 + j) * 128;
        #pragma unroll 4
        for (int k = 0; k < 128; k++) {
            float gk = gbuf[k], hk = hbuf[k];
            gir = fmaf(wi0[k], gk, gir);
            giz = fmaf(wi1[k], gk, giz);
            gin = fmaf(wi2[k], gk, gin);
            ghr = fmaf(wh0[k], hk, ghr);
            ghz = fmaf(wh1[k], hk, ghz);
            ghn = fmaf(wh2[k], hk, ghn);
        }
        float r  = 1.0f / (1.0f + expf(-(gir + ghr)));
        float z  = 1.0f / (1.0f + expf(-(giz + ghz)));
        float nn = tanhf(gin + r * ghn);
        float hn = (1.0f - z) * nn + z * hbuf[j];
        __syncthreads();
        hbuf[j] = hn;
        __syncthreads();
    }

    float o = b_head[j];
    const float* wr = W_head + (size_t)j * 128;
    #pragma unroll 4
    for (int k = 0; k < 128; k++) o = fmaf(wr[k], hbuf[k], o);
    out[j] = o;
}

// ---------------- launch ----------------
extern "C" void kernel_launch(void* const* d_in, const int* in_sizes, int n_in,
                              void* d_out, int out_size)
{
    const float* x_seq  = (const float*)d_in[0];
    const int*   ei_seq = (const int*)  d_in[1];
    const float* W1     = (const float*)d_in[2];
    const float* b1     = (const float*)d_in[3];
    const float* W2     = (const float*)d_in[4];
    const float* b2     = (const float*)d_in[5];
    const float* W_ih   = (const float*)d_in[6];
    const float* W_hh   = (const float*)d_in[7];
    const float* b_ih   = (const float*)d_in[8];
    const float* b_hh   = (const float*)d_in[9];
    const float* W_head = (const float*)d_in[10];
    const float* b_head = (const float*)d_in[11];
    float* out = (float*)d_out;

    __half* bufX;  cudaGetSymbolAddress((void**)&bufX, g_bufX);
    __half* bufA;  cudaGetSymbolAddress((void**)&bufA, g_bufA);
    __half* bufB;  cudaGetSymbolAddress((void**)&bufB, g_bufB);
    float*  dinv;  cudaGetSymbolAddress((void**)&dinv, g_dinv);
    int*    offs;  cudaGetSymbolAddress((void**)&offs, g_offsets);
    float*  gseq;  cudaGetSymbolAddress((void**)&gseq, g_gseq);

    const int GEB = (TOT_EDGES + 255) / 256;
    const int GMB = 1172;
    const int AGX = (N_NODES * 32 + 255) / 256;        // warp per node
    const int APX = 416;

    zero_kernel<<<(TOTAL_CNT + 255) / 256, 256>>>();                            // #0
    count_x2h_kernel<<<4096, 256>>>(ei_seq, x_seq);                             // #1
    scan1_kernel<<<NB_SCAN, 1024>>>();                                          // #2 (also dinv)
    gemm_f16_kernel<<<GMB, 256>>>(bufX, W1, dinv, bufA, TOTAL_ROWS);            // #3 (profiled)
    scan2_kernel<<<1, 1024>>>();                                                // #4
    scan3_kernel<<<NB_SCAN, 1024>>>();                                          // #5
    fill_all_kernel<<<GEB, 256>>>(ei_seq);                                      // #6

    {
        dim3 g(AGX, T_STEPS);
        agg_kernel<<<g, 256>>>(bufA, b1, dinv, offs, bufB);                     // #7
    }
    gemm_f16_kernel<<<GMB, 256>>>(bufB, W2, dinv, bufA, TOTAL_ROWS);            // #8
    {
        dim3 g(APX, T_STEPS);
        agg_pool_kernel<<<g, 256>>>(bufA, b2, dinv, offs, gseq);                // #9
    }

    gru_head_kernel<<<1, 128>>>(W_ih, W_hh, b_ih, b_hh, W_head, b_head, out);   // #10
}